// round 4
// baseline (speedup 1.0000x reference)
#include <cuda_runtime.h>
#include <cuda_bf16.h>
#include <math.h>

// Problem constants
#define T_ 1024
#define B_ 2
#define E_ 1024
#define H_ 16
#define F_ 8
#define D_ 64
#define R_ 2047   // 2*T-1

// ---------------- device scratch (allocation-free rule: __device__ globals) ----
__device__ float g_Win [3 * E_ * E_];          // [3E, E]
__device__ float g_Wpos[E_ * E_];              // [E, E]
__device__ float g_Wout[E_ * E_];              // [E, E]
__device__ float g_bin [3 * E_];
__device__ float g_bpos[E_];
__device__ float g_bout[E_];
__device__ float g_rw  [E_];
__device__ float g_rr  [E_];
__device__ float g_qkv [(size_t)T_ * B_ * 3 * E_];        // [2048, 3072]
__device__ float g_r   [(size_t)4096 * E_];               // [R*B rows (4094 used), 1024]
__device__ float g_S   [(size_t)B_ * H_ * T_ * T_];       // [32, 1024, 1024] scores -> probs
__device__ float g_BD  [(size_t)B_ * H_ * T_ * R_];       // [32, 1024, 2047]
__device__ float g_ctx [(size_t)T_ * B_ * E_];            // [2048, 1024]

// ---------------- hypernet matvec: out[i] = dot(W[i*8 .. i*8+7], factor) -------
__global__ void hyper_mv(const float* __restrict__ W, const float* __restrict__ fac,
                         float* __restrict__ out, int n) {
    float f0 = fac[0], f1 = fac[1], f2 = fac[2], f3 = fac[3];
    float f4 = fac[4], f5 = fac[5], f6 = fac[6], f7 = fac[7];
    for (int i = blockIdx.x * blockDim.x + threadIdx.x; i < n; i += gridDim.x * blockDim.x) {
        const float4* w = (const float4*)(W + (size_t)i * 8);
        float4 w0 = w[0], w1 = w[1];
        out[i] = w0.x*f0 + w0.y*f1 + w0.z*f2 + w0.w*f3
               + w1.x*f4 + w1.y*f5 + w1.z*f6 + w1.w*f7;
    }
}

// ---------------- generic projection GEMM: C[M,N] = A[M,K] @ W[N,K]^T + bias ---
// 128x128 tile, KT=8, 256 threads (16x16), 8x8 micro-tile with j split 4+4.
// Double-buffered smem with register prefetch: one __syncthreads per k-tile.
__global__ __launch_bounds__(256) void gemm_nt(
    const float* __restrict__ A, const float* __restrict__ W,
    const float* __restrict__ bias, float* __restrict__ C,
    int M, int N, int K)
{
    __shared__ float As[2][8][132];
    __shared__ float Bs[2][8][132];
    const int tid = threadIdx.x;
    const int tx = tid & 15, ty = tid >> 4;
    const int i0 = blockIdx.y * 128, j0 = blockIdx.x * 128;
    const int ar  = tid >> 1;      // 0..127 row in tile
    const int akq = tid & 1;       // k-quad

    const int  arow   = i0 + ar;
    const bool aok    = (arow < M);
    const float* Aptr = A + (size_t)(aok ? arow : 0) * K + akq * 4;
    const float* Bptr = W + (size_t)(j0 + ar) * K + akq * 4;

    float acc[8][8];
#pragma unroll
    for (int ii = 0; ii < 8; ii++)
#pragma unroll
        for (int jj = 0; jj < 8; jj++) acc[ii][jj] = 0.f;

    // prefetch tile 0 -> buffer 0
    float4 av = aok ? *(const float4*)(Aptr) : make_float4(0.f,0.f,0.f,0.f);
    float4 bv = *(const float4*)(Bptr);
    As[0][akq*4+0][ar] = av.x; As[0][akq*4+1][ar] = av.y;
    As[0][akq*4+2][ar] = av.z; As[0][akq*4+3][ar] = av.w;
    Bs[0][akq*4+0][ar] = bv.x; Bs[0][akq*4+1][ar] = bv.y;
    Bs[0][akq*4+2][ar] = bv.z; Bs[0][akq*4+3][ar] = bv.w;
    __syncthreads();

    const int nIter = K >> 3;
    for (int it = 0; it < nIter; it++) {
        const int cur = it & 1;
        const bool has = (it + 1 < nIter);

        // issue next tile's global loads early (overlap with compute)
        float4 avn, bvn;
        if (has) {
            int k0n = (it + 1) << 3;
            avn = aok ? *(const float4*)(Aptr + k0n) : make_float4(0.f,0.f,0.f,0.f);
            bvn = *(const float4*)(Bptr + k0n);
        }

#pragma unroll
        for (int kk = 0; kk < 8; kk++) {
            float4 a0 = *(const float4*)&As[cur][kk][8*ty];
            float4 a1 = *(const float4*)&As[cur][kk][8*ty + 4];
            float4 b0 = *(const float4*)&Bs[cur][kk][4*tx];
            float4 b1 = *(const float4*)&Bs[cur][kk][64 + 4*tx];
            float a[8] = {a0.x, a0.y, a0.z, a0.w, a1.x, a1.y, a1.z, a1.w};
            float b[8] = {b0.x, b0.y, b0.z, b0.w, b1.x, b1.y, b1.z, b1.w};
#pragma unroll
            for (int ii = 0; ii < 8; ii++)
#pragma unroll
                for (int jj = 0; jj < 8; jj++)
                    acc[ii][jj] = fmaf(a[ii], b[jj], acc[ii][jj]);
        }

        if (has) {
            const int nxt = cur ^ 1;
            As[nxt][akq*4+0][ar] = avn.x; As[nxt][akq*4+1][ar] = avn.y;
            As[nxt][akq*4+2][ar] = avn.z; As[nxt][akq*4+3][ar] = avn.w;
            Bs[nxt][akq*4+0][ar] = bvn.x; Bs[nxt][akq*4+1][ar] = bvn.y;
            Bs[nxt][akq*4+2][ar] = bvn.z; Bs[nxt][akq*4+3][ar] = bvn.w;
            __syncthreads();
        }
    }

    float bb[8];
#pragma unroll
    for (int jj = 0; jj < 4; jj++) {
        bb[jj]     = bias[j0 + 4*tx + jj];
        bb[4 + jj] = bias[j0 + 64 + 4*tx + jj];
    }
#pragma unroll
    for (int ii = 0; ii < 8; ii++) {
        int row = i0 + 8*ty + ii;
        if (row < M) {
            float* crow = C + (size_t)row * N;
            float4 o0 = make_float4(acc[ii][0]+bb[0], acc[ii][1]+bb[1], acc[ii][2]+bb[2], acc[ii][3]+bb[3]);
            float4 o1 = make_float4(acc[ii][4]+bb[4], acc[ii][5]+bb[5], acc[ii][6]+bb[6], acc[ii][7]+bb[7]);
            *(float4*)(crow + j0 + 4*tx)      = o0;
            *(float4*)(crow + j0 + 64 + 4*tx) = o1;
        }
    }
}

// ---------------- batched per-head GEMM (K=D=64): -----------------------------
// C[bh][i][j] = sum_d (A[i,bh,d] + add[h,d]) * Bv[j,bh,d]
// 128x128 tile, 2 k-iters of 32, register prefetch of second k-tile.
// band != 0 => BD mode: skip j-tiles outside the rel-shift band.
__global__ __launch_bounds__(256) void gemm_heads(
    const float* __restrict__ Abase, int aBatch, int aRow,
    const float* __restrict__ addvec,
    const float* __restrict__ Bbase, int bBatch, int bRow,
    float* __restrict__ Cbase, int N, int band)
{
    __shared__ float As[32][132];
    __shared__ float Bs[32][132];
    const int i0 = blockIdx.y * 128, j0 = blockIdx.x * 128;

    if (band) {
        // tile [j0, j0+127] vs needed band [T_-128-i0, 2*T_-2-i0]
        if (j0 + 127 < T_ - 128 - i0 || j0 > 2 * T_ - 2 - i0) return;
    }

    const int bh = blockIdx.z;
    const int b = bh / H_, h = bh % H_;
    const float* Ap = Abase + (size_t)b * aBatch + h * 64;
    const float* Bp = Bbase + (size_t)b * bBatch + h * 64;
    const float* Addp = addvec + h * 64;
    float* Cp = Cbase + (size_t)bh * T_ * N;

    const int tid = threadIdx.x;
    const int tx = tid & 15, ty = tid >> 4;
    const int lq = tid & 7;    // d-quad 0..7
    const int lr = tid >> 3;   // 0..31

    float acc[8][8];
#pragma unroll
    for (int ii = 0; ii < 8; ii++)
#pragma unroll
        for (int jj = 0; jj < 8; jj++) acc[ii][jj] = 0.f;

    // ---- stage k-tile 0 (d = 0..31) into smem
    {
        float4 addq = *(const float4*)(Addp + lq * 4);
#pragma unroll
        for (int rep = 0; rep < 4; rep++) {
            int row = rep * 32 + lr;
            float4 v = *(const float4*)(Ap + (size_t)(i0 + row) * aRow + lq * 4);
            As[lq*4+0][row] = v.x + addq.x;
            As[lq*4+1][row] = v.y + addq.y;
            As[lq*4+2][row] = v.z + addq.z;
            As[lq*4+3][row] = v.w + addq.w;
        }
#pragma unroll
        for (int rep = 0; rep < 4; rep++) {
            int row = rep * 32 + lr;
            int jg = j0 + row;
            float4 v = make_float4(0.f, 0.f, 0.f, 0.f);
            if (jg < N) v = *(const float4*)(Bp + (size_t)jg * bRow + lq * 4);
            Bs[lq*4+0][row] = v.x;
            Bs[lq*4+1][row] = v.y;
            Bs[lq*4+2][row] = v.z;
            Bs[lq*4+3][row] = v.w;
        }
    }
    __syncthreads();

    // ---- prefetch k-tile 1 (d = 32..63) into registers (overlaps compute 0)
    float4 a1r[4], b1r[4];
    float4 addq1 = *(const float4*)(Addp + 32 + lq * 4);
#pragma unroll
    for (int rep = 0; rep < 4; rep++) {
        int row = rep * 32 + lr;
        a1r[rep] = *(const float4*)(Ap + (size_t)(i0 + row) * aRow + 32 + lq * 4);
        int jg = j0 + row;
        b1r[rep] = make_float4(0.f, 0.f, 0.f, 0.f);
        if (jg < N) b1r[rep] = *(const float4*)(Bp + (size_t)jg * bRow + 32 + lq * 4);
    }

    // ---- compute k-tile 0
#pragma unroll
    for (int dd = 0; dd < 32; dd++) {
        float4 a0 = *(const float4*)&As[dd][8*ty];
        float4 a1 = *(const float4*)&As[dd][8*ty + 4];
        float4 b0 = *(const float4*)&Bs[dd][4*tx];
        float4 b1 = *(const float4*)&Bs[dd][64 + 4*tx];
        float a[8] = {a0.x, a0.y, a0.z, a0.w, a1.x, a1.y, a1.z, a1.w};
        float b[8] = {b0.x, b0.y, b0.z, b0.w, b1.x, b1.y, b1.z, b1.w};
#pragma unroll
        for (int ii = 0; ii < 8; ii++)
#pragma unroll
            for (int jj = 0; jj < 8; jj++)
                acc[ii][jj] = fmaf(a[ii], b[jj], acc[ii][jj]);
    }
    __syncthreads();

    // ---- store k-tile 1 from registers
#pragma unroll
    for (int rep = 0; rep < 4; rep++) {
        int row = rep * 32 + lr;
        As[lq*4+0][row] = a1r[rep].x + addq1.x;
        As[lq*4+1][row] = a1r[rep].y + addq1.y;
        As[lq*4+2][row] = a1r[rep].z + addq1.z;
        As[lq*4+3][row] = a1r[rep].w + addq1.w;
        Bs[lq*4+0][row] = b1r[rep].x;
        Bs[lq*4+1][row] = b1r[rep].y;
        Bs[lq*4+2][row] = b1r[rep].z;
        Bs[lq*4+3][row] = b1r[rep].w;
    }
    __syncthreads();

    // ---- compute k-tile 1
#pragma unroll
    for (int dd = 0; dd < 32; dd++) {
        float4 a0 = *(const float4*)&As[dd][8*ty];
        float4 a1 = *(const float4*)&As[dd][8*ty + 4];
        float4 b0 = *(const float4*)&Bs[dd][4*tx];
        float4 b1 = *(const float4*)&Bs[dd][64 + 4*tx];
        float a[8] = {a0.x, a0.y, a0.z, a0.w, a1.x, a1.y, a1.z, a1.w};
        float b[8] = {b0.x, b0.y, b0.z, b0.w, b1.x, b1.y, b1.z, b1.w};
#pragma unroll
        for (int ii = 0; ii < 8; ii++)
#pragma unroll
            for (int jj = 0; jj < 8; jj++)
                acc[ii][jj] = fmaf(a[ii], b[jj], acc[ii][jj]);
    }

    const bool vec = ((N & 3) == 0) && (j0 + 128 <= N);
#pragma unroll
    for (int ii = 0; ii < 8; ii++) {
        int row = i0 + 8*ty + ii;
        float* crow = Cp + (size_t)row * N;
        if (vec) {
            *(float4*)(crow + j0 + 4*tx)      = make_float4(acc[ii][0], acc[ii][1], acc[ii][2], acc[ii][3]);
            *(float4*)(crow + j0 + 64 + 4*tx) = make_float4(acc[ii][4], acc[ii][5], acc[ii][6], acc[ii][7]);
        } else {
#pragma unroll
            for (int jj = 0; jj < 4; jj++) {
                int j1 = j0 + 4*tx + jj;
                int j2 = j0 + 64 + 4*tx + jj;
                if (j1 < N) crow[j1] = acc[ii][jj];
                if (j2 < N) crow[j2] = acc[ii][4 + jj];
            }
        }
    }
}

// ---------------- fused shift + scale + softmax --------------------------------
// P[bh][i][j] = softmax_j( (S[bh][i][j] + BD[bh][i][j + 1023 - i]) * 0.125 )
__global__ __launch_bounds__(256) void softmax_rows(
    const float* __restrict__ S, const float* __restrict__ BD, float* __restrict__ P)
{
    const int i = blockIdx.x;
    const int bh = blockIdx.y;
    const int tid = threadIdx.x;
    const float* srow = S  + ((size_t)bh * T_ + i) * T_;
    const float* brow = BD + ((size_t)bh * T_ + i) * R_ + (T_ - 1 - i);

    float4 s4 = *(const float4*)(srow + tid * 4);
    float x0 = (s4.x + brow[tid*4+0]) * 0.125f;
    float x1 = (s4.y + brow[tid*4+1]) * 0.125f;
    float x2 = (s4.z + brow[tid*4+2]) * 0.125f;
    float x3 = (s4.w + brow[tid*4+3]) * 0.125f;

    __shared__ float red[8];
    const int lane = tid & 31, wid = tid >> 5;

    float m = fmaxf(fmaxf(x0, x1), fmaxf(x2, x3));
#pragma unroll
    for (int off = 16; off > 0; off >>= 1) m = fmaxf(m, __shfl_xor_sync(0xffffffffu, m, off));
    if (lane == 0) red[wid] = m;
    __syncthreads();
    m = red[0];
#pragma unroll
    for (int w = 1; w < 8; w++) m = fmaxf(m, red[w]);
    __syncthreads();

    float e0 = __expf(x0 - m), e1 = __expf(x1 - m), e2 = __expf(x2 - m), e3 = __expf(x3 - m);
    float s = e0 + e1 + e2 + e3;
#pragma unroll
    for (int off = 16; off > 0; off >>= 1) s += __shfl_xor_sync(0xffffffffu, s, off);
    if (lane == 0) red[wid] = s;
    __syncthreads();
    s = red[0];
#pragma unroll
    for (int w = 1; w < 8; w++) s += red[w];

    float inv = 1.0f / s;
    float* prow = P + ((size_t)bh * T_ + i) * T_;
    *(float4*)(prow + tid * 4) = make_float4(e0 * inv, e1 * inv, e2 * inv, e3 * inv);
}

// ---------------- attn @ V: ctx[i][b][h*64+d] = sum_j P[bh][i][j] * v[j,b,h,d]
// 128(i) x 64(d) tile per bh, KT=16, double-buffered smem + register prefetch.
__global__ __launch_bounds__(256) void av_gemm(
    const float* __restrict__ P, const float* __restrict__ Vbase, float* __restrict__ ctx)
{
    __shared__ float As[2][16][132];
    __shared__ float Bs[2][16][68];
    const int bh = blockIdx.z;
    const int b = bh / H_, h = bh % H_;
    const float* Pp = P + (size_t)bh * T_ * T_;
    const float* Vp = Vbase + (size_t)b * (3 * E_) + h * 64;   // row j at Vp + j*6144
    const int i0 = blockIdx.x * 128;
    const int tid = threadIdx.x;
    const int tx = tid & 15, ty = tid >> 4;

    float acc[8][4];
#pragma unroll
    for (int ii = 0; ii < 8; ii++)
#pragma unroll
        for (int jj = 0; jj < 4; jj++) acc[ii][jj] = 0.f;

    const int brow = tid >> 4, bdq = tid & 15;
    const int ar0 = tid >> 2, akq = tid & 3;            // rep0 A indices
    const int ar1 = (256 + tid) >> 2;                    // rep1 A row

    // prefetch k-tile 0 -> buffer 0
    {
        float4 v0 = *(const float4*)(Pp + (size_t)(i0 + ar0) * T_ + akq * 4);
        float4 v1 = *(const float4*)(Pp + (size_t)(i0 + ar1) * T_ + akq * 4);
        As[0][akq*4+0][ar0] = v0.x; As[0][akq*4+1][ar0] = v0.y;
        As[0][akq*4+2][ar0] = v0.z; As[0][akq*4+3][ar0] = v0.w;
        As[0][akq*4+0][ar1] = v1.x; As[0][akq*4+1][ar1] = v1.y;
        As[0][akq*4+2][ar1] = v1.z; As[0][akq*4+3][ar1] = v1.w;
        float4 bv = *(const float4*)(Vp + (size_t)brow * (B_ * 3 * E_) + bdq * 4);
        *(float4*)&Bs[0][brow][bdq * 4] = bv;
    }
    __syncthreads();

    for (int it = 0; it < 64; it++) {
        const int cur = it & 1;
        const bool has = (it < 63);
        float4 v0n, v1n, bvn;
        if (has) {
            int k0n = (it + 1) << 4;
            v0n = *(const float4*)(Pp + (size_t)(i0 + ar0) * T_ + k0n + akq * 4);
            v1n = *(const float4*)(Pp + (size_t)(i0 + ar1) * T_ + k0n + akq * 4);
            bvn = *(const float4*)(Vp + (size_t)(k0n + brow) * (B_ * 3 * E_) + bdq * 4);
        }

#pragma unroll
        for (int kk = 0; kk < 16; kk++) {
            float4 a0 = *(const float4*)&As[cur][kk][8*ty];
            float4 a1 = *(const float4*)&As[cur][kk][8*ty + 4];
            float4 b0 = *(const float4*)&Bs[cur][kk][4*tx];
            float a[8] = {a0.x, a0.y, a0.z, a0.w, a1.x, a1.y, a1.z, a1.w};
            float bb[4] = {b0.x, b0.y, b0.z, b0.w};
#pragma unroll
            for (int ii = 0; ii < 8; ii++)
#pragma unroll
                for (int jj = 0; jj < 4; jj++)
                    acc[ii][jj] = fmaf(a[ii], bb[jj], acc[ii][jj]);
        }

        if (has) {
            const int nxt = cur ^ 1;
            As[nxt][akq*4+0][ar0] = v0n.x; As[nxt][akq*4+1][ar0] = v0n.y;
            As[nxt][akq*4+2][ar0] = v0n.z; As[nxt][akq*4+3][ar0] = v0n.w;
            As[nxt][akq*4+0][ar1] = v1n.x; As[nxt][akq*4+1][ar1] = v1n.y;
            As[nxt][akq*4+2][ar1] = v1n.z; As[nxt][akq*4+3][ar1] = v1n.w;
            *(float4*)&Bs[nxt][brow][bdq * 4] = bvn;
            __syncthreads();
        }
    }

#pragma unroll
    for (int ii = 0; ii < 8; ii++) {
        int row = i0 + 8*ty + ii;   // i (query time index)
        float* dst = ctx + ((size_t)row * B_ + b) * E_ + h * 64 + 4 * tx;
        *(float4*)dst = make_float4(acc[ii][0], acc[ii][1], acc[ii][2], acc[ii][3]);
    }
}

// ---------------- host launcher -------------------------------------------------
extern "C" void kernel_launch(void* const* d_in, const int* in_sizes, int n_in,
                              void* d_out, int out_size) {
    const float* input  = (const float*)d_in[0];   // [T,B,E]
    const float* pos    = (const float*)d_in[1];   // [R,B,E]
    const float* factor = (const float*)d_in[2];   // [F]
    const float* in_w   = (const float*)d_in[3];   // [3E*E, F]
    const float* pos_w  = (const float*)d_in[4];   // [E*E, F]
    const float* out_w  = (const float*)d_in[5];   // [E*E, F]
    const float* in_b   = (const float*)d_in[6];   // [3E, F]
    const float* pos_b  = (const float*)d_in[7];   // [E, F]
    const float* out_b  = (const float*)d_in[8];   // [E, F]
    const float* rwb    = (const float*)d_in[9];   // [E, F]
    const float* rrb    = (const float*)d_in[10];  // [E, F]
    float* out = (float*)d_out;

    float *pWin, *pWpos, *pWout, *pbin, *pbpos, *pbout, *prw, *prr;
    float *pqkv, *pr, *pS, *pBD, *pctx;
    cudaGetSymbolAddress((void**)&pWin,  g_Win);
    cudaGetSymbolAddress((void**)&pWpos, g_Wpos);
    cudaGetSymbolAddress((void**)&pWout, g_Wout);
    cudaGetSymbolAddress((void**)&pbin,  g_bin);
    cudaGetSymbolAddress((void**)&pbpos, g_bpos);
    cudaGetSymbolAddress((void**)&pbout, g_bout);
    cudaGetSymbolAddress((void**)&prw,   g_rw);
    cudaGetSymbolAddress((void**)&prr,   g_rr);
    cudaGetSymbolAddress((void**)&pqkv,  g_qkv);
    cudaGetSymbolAddress((void**)&pr,    g_r);
    cudaGetSymbolAddress((void**)&pS,    g_S);
    cudaGetSymbolAddress((void**)&pBD,   g_BD);
    cudaGetSymbolAddress((void**)&pctx,  g_ctx);

    // 1) hypernetwork: generate effective weights
    hyper_mv<<<4096, 256>>>(in_w,  factor, pWin,  3 * E_ * E_);
    hyper_mv<<<2048, 256>>>(pos_w, factor, pWpos, E_ * E_);
    hyper_mv<<<2048, 256>>>(out_w, factor, pWout, E_ * E_);
    hyper_mv<<<12,   256>>>(in_b,  factor, pbin,  3 * E_);
    hyper_mv<<<4,    256>>>(pos_b, factor, pbpos, E_);
    hyper_mv<<<4,    256>>>(out_b, factor, pbout, E_);
    hyper_mv<<<4,    256>>>(rwb,   factor, prw,   E_);
    hyper_mv<<<4,    256>>>(rrb,   factor, prr,   E_);

    // 2) qkv = input @ W_in^T + b_in : [2048, 3072]
    gemm_nt<<<dim3(24, 16), 256>>>(input, pWin, pbin, pqkv, T_ * B_, 3 * E_, E_);

    // 3) r = pos @ W_pos^T + b_pos : [4094, 1024]
    gemm_nt<<<dim3(8, 32), 256>>>(pos, pWpos, pbpos, pr, R_ * B_, E_, E_);

    // 4) AC[bh,i,j] = sum_d (q + rw) . k   -> g_S   (full, band=0)
    gemm_heads<<<dim3(8, 8, 32), 256>>>(pqkv, 3 * E_, B_ * 3 * E_, prw,
                                        pqkv + E_, 3 * E_, B_ * 3 * E_,
                                        pS, T_, 0);

    // 5) BD[bh,i,r] = sum_d (q + rr) . rpos -> g_BD  (band-limited, band=1)
    gemm_heads<<<dim3(16, 8, 32), 256>>>(pqkv, 3 * E_, B_ * 3 * E_, prr,
                                         pr, E_, B_ * E_,
                                         pBD, R_, 1);

    // 6) softmax((AC + shift(BD)) * 1/sqrt(D)) -> g_S in place
    softmax_rows<<<dim3(T_, B_ * H_), 256>>>(pS, pBD, pS);

    // 7) ctx = attn @ v
    av_gemm<<<dim3(8, 1, 32), 256>>>(pS, pqkv + 2 * E_, pctx);

    // 8) out = ctx @ W_out^T + b_out
    gemm_nt<<<dim3(8, 16), 256>>>(pctx, pWout, pbout, out, T_ * B_, E_, E_);
}